// round 6
// baseline (speedup 1.0000x reference)
#include <cuda_runtime.h>
#include <cstdint>
#include <math.h>

// NT-Xent loss, B=2048, D=512, N=4096, T=0.5.
// loss = (1/N) * sum_i [ 2 + log( sum_{j != i} exp(sim_ij - 2) ) - sim_{i,partner(i)} ]
// sim = (zn zn^T)/T in [-2,2] => fixed shift 2, single pass, no row max.
// FP8 e4m3 mma.sync GEMM over UPPER-TRIANGULAR tiles only (sim symmetric):
// each off-diagonal tile contributes to rowsum[rows] AND rowsum[cols].
// m16n8k32 e4m3 fragments are byte-identical to m16n8k16 b16 fragments,
// so the bf16 ldmatrix addressing carries over unchanged.

#define Bz 2048
#define Nn 4096
#define Dd 512

__device__ uint32_t g_znq[Nn * (Dd / 4)];  // e4m3 normalized (2 MB, L2-resident)
__device__ float g_rowsum[Nn];             // sum_{j!=i} exp(sim_ij - 2)
__device__ float g_pos[Nn];                // dot(zn_i, zn_partner)

// ---------------------------------------------------------------------------
// exp(2a-2) on the FMA pipe (no MUFU). 2^y, y=(a-1)*2log2e in [-5.9, 0.1];
// magic-add range reduction + deg-5 poly (rel err ~3e-6).
// ---------------------------------------------------------------------------
__device__ __forceinline__ float exp_sim(float a) {
    float y = fmaf(a, 2.8853900817779268f, -2.8853900817779268f);
    float z = y + 12582912.0f;
    float f = y - (z - 12582912.0f);
    int ei = (__float_as_int(z) + (127 - 0x400000)) << 23;
    float p = fmaf(f, 1.3333558146428443e-3f, 9.6181291076284771e-3f);
    p = fmaf(f, p, 5.5504108664821580e-2f);
    p = fmaf(f, p, 2.4022650695910071e-1f);
    p = fmaf(f, p, 6.9314718055994531e-1f);
    p = fmaf(f, p, 1.0f);
    return p * __int_as_float(ei);
}

// pack 4 fp32 -> 4 e4m3 in one u32 (byte0 = v.x)
__device__ __forceinline__ uint32_t pack4_e4m3(float x, float y, float z, float w) {
    uint32_t r;
    asm("{ .reg .b16 lo, hi;\n\t"
        "cvt.rn.satfinite.e4m3x2.f32 lo, %2, %1;\n\t"
        "cvt.rn.satfinite.e4m3x2.f32 hi, %4, %3;\n\t"
        "mov.b32 %0, {lo, hi}; }"
        : "=r"(r) : "f"(x), "f"(y), "f"(z), "f"(w));
    return r;
}

// ---------------------------------------------------------------------------
// Kernel 1: row-normalize -> e4m3. One warp per row, no block sync.
// grid 512 x 256 threads (8 warps = 8 rows per block).
// ---------------------------------------------------------------------------
__global__ __launch_bounds__(256) void k_normalize(const float* __restrict__ zi,
                                                   const float* __restrict__ zj,
                                                   float* __restrict__ out) {
    int row = (blockIdx.x * 256 + threadIdx.x) >> 5;
    int l = threadIdx.x & 31;
    const float4* src = (row < Bz)
        ? reinterpret_cast<const float4*>(zi + (size_t)row * Dd)
        : reinterpret_cast<const float4*>(zj + (size_t)(row - Bz) * Dd);
    float4 v0 = src[l];
    float4 v1 = src[l + 32];
    float4 v2 = src[l + 64];
    float4 v3 = src[l + 96];
    float ss = v0.x * v0.x + v0.y * v0.y + v0.z * v0.z + v0.w * v0.w;
    ss += v1.x * v1.x + v1.y * v1.y + v1.z * v1.z + v1.w * v1.w;
    ss += v2.x * v2.x + v2.y * v2.y + v2.z * v2.z + v2.w * v2.w;
    ss += v3.x * v3.x + v3.y * v3.y + v3.z * v3.z + v3.w * v3.w;
#pragma unroll
    for (int o = 16; o > 0; o >>= 1) ss += __shfl_xor_sync(0xffffffffu, ss, o);
    float inv = 1.0f / fmaxf(sqrtf(ss), 1e-8f);
    uint32_t* dst = g_znq + (size_t)row * 128;
    dst[l]      = pack4_e4m3(v0.x * inv, v0.y * inv, v0.z * inv, v0.w * inv);
    dst[l + 32] = pack4_e4m3(v1.x * inv, v1.y * inv, v1.z * inv, v1.w * inv);
    dst[l + 64] = pack4_e4m3(v2.x * inv, v2.y * inv, v2.z * inv, v2.w * inv);
    dst[l + 96] = pack4_e4m3(v3.x * inv, v3.y * inv, v3.z * inv, v3.w * inv);
    if (l == 0) g_rowsum[row] = 0.0f;
    if (l == 0 && row == 0) out[0] = 0.0f;
}

// ---------------------------------------------------------------------------
// Kernel 2: upper-triangular fused sim-exp-rowsum (e4m3).
// 528 CTAs; CTA k -> tile (ti, tj), tj >= ti, 128x128 per tile.
// 8 warps (2x4), warp tile 64x32, 8-stage K pipeline (64B = 64 fp8 per stage),
// cp.async double buffer. SMEM row pitch 80B.
// ---------------------------------------------------------------------------
#define PITCH 80
#define TILE_BYTES (128 * PITCH)
#define NSTAGE 8

__global__ __launch_bounds__(256) void k_simexp() {
    __shared__ __align__(128) char sA[2][TILE_BYTES];
    __shared__ __align__(128) char sB[2][TILE_BYTES];
    __shared__ float rs_row[128];
    __shared__ float rs_col[128];

    int tid = threadIdx.x;
    int l = tid & 31;
    int wid = tid >> 5;
    int wm = wid >> 2;   // 0..1
    int wn = wid & 3;    // 0..3

    // triangular decode: k -> (ti, tj), start(ti) = 32*ti - ti*(ti-1)/2
    int k = blockIdx.x;
    int ti = (int)((65.0f - sqrtf(4225.0f - 8.0f * (float)k)) * 0.5f);
    while ((ti + 1) * 32 - ((ti + 1) * ti) / 2 <= k) ++ti;
    while (ti * 32 - (ti * (ti - 1)) / 2 > k) --ti;
    int tj = ti + (k - (ti * 32 - (ti * (ti - 1)) / 2));
    int r0 = ti * 128, c0 = tj * 128;
    bool dual = (ti != tj);
    bool postile = (tj - ti) == 16;
    const char* zb = (const char*)g_znq;   // row stride 512B

    if (tid < 128) { rs_row[tid] = 0.0f; rs_col[tid] = 0.0f; }

    uint32_t sA0 = (uint32_t)__cvta_generic_to_shared(&sA[0][0]);
    uint32_t sB0 = (uint32_t)__cvta_generic_to_shared(&sB[0][0]);

    uint32_t aoff = (uint32_t)((64 * wm + (l & 15)) * PITCH + ((l >> 4) & 1) * 16);
    uint32_t boff = (uint32_t)((32 * wn + (l & 7) + ((l >> 4) & 1) * 8) * PITCH
                               + ((l >> 3) & 1) * 16);

    float acc[4][4][4];
#pragma unroll
    for (int a = 0; a < 4; ++a)
#pragma unroll
        for (int b = 0; b < 4; ++b)
#pragma unroll
            for (int d = 0; d < 4; ++d) acc[a][b][d] = 0.0f;

    auto load_stage = [&](int s) {
        uint32_t koff = (uint32_t)s * 64u;   // 64 fp8 per stage
#pragma unroll
        for (int m = 0; m < 4; ++m) {
            int ch = tid + m * 256;          // 0..1023 16B chunks
            int half = ch >> 9;              // 0=A, 1=B
            int e = ch & 511;
            int row = e >> 2, seg = e & 3;
            uint32_t dst = (half ? sB0 : sA0)
                         + (uint32_t)(s & 1) * (uint32_t)TILE_BYTES
                         + (uint32_t)row * PITCH + (uint32_t)seg * 16u;
            const char* src = zb + (size_t)((half ? c0 : r0) + row) * 512u
                            + koff + (uint32_t)seg * 16u;
            asm volatile("cp.async.cg.shared.global [%0], [%1], 16;"
                         :: "r"(dst), "l"(src) : "memory");
        }
        asm volatile("cp.async.commit_group;" ::: "memory");
    };

    load_stage(0);
    for (int s = 0; s < NSTAGE; ++s) {
        if (s + 1 < NSTAGE) {
            load_stage(s + 1);
            asm volatile("cp.async.wait_group 1;" ::: "memory");
        } else {
            asm volatile("cp.async.wait_group 0;" ::: "memory");
        }
        __syncthreads();

        uint32_t Ab = sA0 + (uint32_t)(s & 1) * (uint32_t)TILE_BYTES;
        uint32_t Bb = sB0 + (uint32_t)(s & 1) * (uint32_t)TILE_BYTES;
#pragma unroll
        for (int ks = 0; ks < 2; ++ks) {
            uint32_t kb = (uint32_t)ks * 32u;    // K=32 fp8 = 32 bytes
            uint32_t a[4][4], bb[2][4];
#pragma unroll
            for (int mt = 0; mt < 4; ++mt)
                asm volatile(
                    "ldmatrix.sync.aligned.m8n8.x4.shared.b16 {%0,%1,%2,%3}, [%4];"
                    : "=r"(a[mt][0]), "=r"(a[mt][1]), "=r"(a[mt][2]), "=r"(a[mt][3])
                    : "r"(Ab + aoff + (uint32_t)mt * (16u * PITCH) + kb));
#pragma unroll
            for (int ng = 0; ng < 2; ++ng)
                asm volatile(
                    "ldmatrix.sync.aligned.m8n8.x4.shared.b16 {%0,%1,%2,%3}, [%4];"
                    : "=r"(bb[ng][0]), "=r"(bb[ng][1]), "=r"(bb[ng][2]), "=r"(bb[ng][3])
                    : "r"(Bb + boff + (uint32_t)ng * (16u * PITCH) + kb));
#pragma unroll
            for (int mt = 0; mt < 4; ++mt)
#pragma unroll
                for (int nt = 0; nt < 4; ++nt) {
                    uint32_t b0 = bb[nt >> 1][(nt & 1) * 2];
                    uint32_t b1 = bb[nt >> 1][(nt & 1) * 2 + 1];
                    asm volatile(
                        "mma.sync.aligned.m16n8k32.row.col.f32.e4m3.e4m3.f32 "
                        "{%0,%1,%2,%3}, {%4,%5,%6,%7}, {%8,%9}, {%0,%1,%2,%3};"
                        : "+f"(acc[mt][nt][0]), "+f"(acc[mt][nt][1]),
                          "+f"(acc[mt][nt][2]), "+f"(acc[mt][nt][3])
                        : "r"(a[mt][0]), "r"(a[mt][1]), "r"(a[mt][2]), "r"(a[mt][3]),
                          "r"(b0), "r"(b1));
                }
        }
        __syncthreads();
    }

    // Epilogue. D row = 64wm + 16mt + (l>>2) + 8*half ; col = 32wn + 8nt + (l&3)*2.
    float vcol[4][2];
#pragma unroll
    for (int nt = 0; nt < 4; ++nt) { vcol[nt][0] = 0.0f; vcol[nt][1] = 0.0f; }

#pragma unroll
    for (int mt = 0; mt < 4; ++mt) {
#pragma unroll
        for (int half = 0; half < 2; ++half) {
            int rl = 64 * wm + 16 * mt + (l >> 2) + 8 * half;
            int gr = r0 + rl;
            float v = 0.0f;
#pragma unroll
            for (int nt = 0; nt < 4; ++nt) {
                int gc = c0 + 32 * wn + 8 * nt + (l & 3) * 2;
                float d0 = acc[mt][nt][half * 2 + 0];
                float d1 = acc[mt][nt][half * 2 + 1];
                float e0 = exp_sim(d0);
                float e1 = exp_sim(d1);
                if (postile) {   // positive-pair diagonal lives in these tiles
                    if (gc == gr + Bz)     { g_pos[gr] = d0; g_pos[gc] = d0; }
                    if (gc + 1 == gr + Bz) { g_pos[gr] = d1; g_pos[gc + 1] = d1; }
                }
                v += (gr == gc) ? 0.0f : e0;
                v += (gr == gc + 1) ? 0.0f : e1;
                vcol[nt][0] += e0;
                vcol[nt][1] += e1;
            }
            v += __shfl_xor_sync(0xffffffffu, v, 1);
            v += __shfl_xor_sync(0xffffffffu, v, 2);
            if ((l & 3) == 0) atomicAdd(&rs_row[rl], v);
        }
    }
    if (dual) {
#pragma unroll
        for (int nt = 0; nt < 4; ++nt) {
            float cv0 = vcol[nt][0], cv1 = vcol[nt][1];
#pragma unroll
            for (int o = 4; o <= 16; o <<= 1) {
                cv0 += __shfl_xor_sync(0xffffffffu, cv0, o);
                cv1 += __shfl_xor_sync(0xffffffffu, cv1, o);
            }
            if ((l >> 2) == 0) {
                int cl = 32 * wn + 8 * nt + (l & 3) * 2;
                atomicAdd(&rs_col[cl], cv0);
                atomicAdd(&rs_col[cl + 1], cv1);
            }
        }
    }
    __syncthreads();
    if (tid < 128) {
        atomicAdd(&g_rowsum[r0 + tid], rs_row[tid]);
        if (dual) atomicAdd(&g_rowsum[c0 + tid], rs_col[tid]);
    }
}

// ---------------------------------------------------------------------------
// Kernel 3: finalize. loss_i = 2 + log(rowsum_i) - 2*pos_i ; mean into out.
// ---------------------------------------------------------------------------
__global__ void k_finalize(float* __restrict__ out) {
    int i = blockIdx.x * 256 + threadIdx.x;
    float term = 2.0f + logf(g_rowsum[i]) - 2.0f * g_pos[i];
    int l = threadIdx.x & 31;
#pragma unroll
    for (int o = 16; o > 0; o >>= 1) term += __shfl_xor_sync(0xffffffffu, term, o);
    __shared__ float red[8];
    if (l == 0) red[threadIdx.x >> 5] = term;
    __syncthreads();
    if (threadIdx.x == 0) {
        float s = 0.0f;
#pragma unroll
        for (int w = 0; w < 8; ++w) s += red[w];
        atomicAdd(out, s * (1.0f / (float)Nn));
    }
}

extern "C" void kernel_launch(void* const* d_in, const int* in_sizes, int n_in,
                              void* d_out, int out_size) {
    const float* zi = (const float*)d_in[0];
    const float* zj = (const float*)d_in[1];
    float* out = (float*)d_out;

    k_normalize<<<512, 256>>>(zi, zj, out);
    k_simexp<<<528, 256>>>();
    k_finalize<<<Nn / 256, 256>>>(out);
}

// round 7
// speedup vs baseline: 1.0372x; 1.0372x over previous
#include <cuda_runtime.h>
#include <cuda_bf16.h>
#include <cstdint>
#include <math.h>

// NT-Xent loss, B=2048, D=512, N=4096, T=0.5.
// loss = (1/N) * sum_i [ 2 + log( sum_{j != i} exp(sim_ij - 2) ) - sim_{i,partner(i)} ]
// sim = (zn zn^T)/T in [-2,2] => fixed shift 2, single pass, no row max.
// bf16 mma.sync GEMM over UPPER-TRIANGULAR tiles (sim symmetric); each
// off-diagonal tile feeds rowsum[rows] AND rowsum[cols]. Triple-buffered
// cp.async pipeline with a single __syncthreads per K stage.

#define Bz 2048
#define Nn 4096
#define Dd 512

__device__ __nv_bfloat16 g_znh[Nn * Dd];   // bf16 normalized (4 MB, L2-resident)
__device__ float g_rowsum[Nn];             // sum_{j!=i} exp(sim_ij - 2)
__device__ float g_pos[Nn];                // dot(zn_i, zn_partner)

// ---------------------------------------------------------------------------
// exp(2a-2) on the FMA pipe (no MUFU). 2^y, y=(a-1)*2log2e in [-5.9, 0.1];
// magic-add range reduction + deg-5 poly (rel err ~3e-6).
// ---------------------------------------------------------------------------
__device__ __forceinline__ float exp_sim(float a) {
    float y = fmaf(a, 2.8853900817779268f, -2.8853900817779268f);
    float z = y + 12582912.0f;
    float f = y - (z - 12582912.0f);
    int ei = (__float_as_int(z) + (127 - 0x400000)) << 23;
    float p = fmaf(f, 1.3333558146428443e-3f, 9.6181291076284771e-3f);
    p = fmaf(f, p, 5.5504108664821580e-2f);
    p = fmaf(f, p, 2.4022650695910071e-1f);
    p = fmaf(f, p, 6.9314718055994531e-1f);
    p = fmaf(f, p, 1.0f);
    return p * __int_as_float(ei);
}

// ---------------------------------------------------------------------------
// Kernel 1: row-normalize -> bf16. One warp per row, no block sync.
// ---------------------------------------------------------------------------
__global__ __launch_bounds__(256) void k_normalize(const float* __restrict__ zi,
                                                   const float* __restrict__ zj,
                                                   float* __restrict__ out) {
    int row = (blockIdx.x * 256 + threadIdx.x) >> 5;
    int l = threadIdx.x & 31;
    const float4* src = (row < Bz)
        ? reinterpret_cast<const float4*>(zi + (size_t)row * Dd)
        : reinterpret_cast<const float4*>(zj + (size_t)(row - Bz) * Dd);
    float4 v0 = src[l];
    float4 v1 = src[l + 32];
    float4 v2 = src[l + 64];
    float4 v3 = src[l + 96];
    float ss = v0.x * v0.x + v0.y * v0.y + v0.z * v0.z + v0.w * v0.w;
    ss += v1.x * v1.x + v1.y * v1.y + v1.z * v1.z + v1.w * v1.w;
    ss += v2.x * v2.x + v2.y * v2.y + v2.z * v2.z + v2.w * v2.w;
    ss += v3.x * v3.x + v3.y * v3.y + v3.z * v3.z + v3.w * v3.w;
#pragma unroll
    for (int o = 16; o > 0; o >>= 1) ss += __shfl_xor_sync(0xffffffffu, ss, o);
    float inv = 1.0f / fmaxf(sqrtf(ss), 1e-8f);
    uint2* dst = reinterpret_cast<uint2*>(g_znh + (size_t)row * Dd);
    __nv_bfloat162 h0, h1;
    uint2 u;
    h0 = __floats2bfloat162_rn(v0.x * inv, v0.y * inv);
    h1 = __floats2bfloat162_rn(v0.z * inv, v0.w * inv);
    u.x = *reinterpret_cast<uint32_t*>(&h0); u.y = *reinterpret_cast<uint32_t*>(&h1);
    dst[l] = u;
    h0 = __floats2bfloat162_rn(v1.x * inv, v1.y * inv);
    h1 = __floats2bfloat162_rn(v1.z * inv, v1.w * inv);
    u.x = *reinterpret_cast<uint32_t*>(&h0); u.y = *reinterpret_cast<uint32_t*>(&h1);
    dst[l + 32] = u;
    h0 = __floats2bfloat162_rn(v2.x * inv, v2.y * inv);
    h1 = __floats2bfloat162_rn(v2.z * inv, v2.w * inv);
    u.x = *reinterpret_cast<uint32_t*>(&h0); u.y = *reinterpret_cast<uint32_t*>(&h1);
    dst[l + 64] = u;
    h0 = __floats2bfloat162_rn(v3.x * inv, v3.y * inv);
    h1 = __floats2bfloat162_rn(v3.z * inv, v3.w * inv);
    u.x = *reinterpret_cast<uint32_t*>(&h0); u.y = *reinterpret_cast<uint32_t*>(&h1);
    dst[l + 96] = u;
    if (l == 0) g_rowsum[row] = 0.0f;
    if (l == 0 && row == 0) out[0] = 0.0f;
}

// ---------------------------------------------------------------------------
// Kernel 2: upper-triangular fused sim-exp-rowsum (bf16).
// 528 CTAs; CTA k -> tile (ti, tj), tj >= ti, 128x128 per tile.
// 8 warps (2x4), warp tile 64x32. 16 K stages of 32 bf16 (64B),
// TRIPLE-buffered cp.async, ONE __syncthreads per stage.
// ---------------------------------------------------------------------------
#define PITCH 80
#define TILE_BYTES (128 * PITCH)
#define NSTAGE 16

__global__ __launch_bounds__(256) void k_simexp() {
    __shared__ __align__(128) char sA[3][TILE_BYTES];
    __shared__ __align__(128) char sB[3][TILE_BYTES];
    __shared__ float rs_row[128];
    __shared__ float rs_col[128];

    int tid = threadIdx.x;
    int l = tid & 31;
    int wid = tid >> 5;
    int wm = wid >> 2;   // 0..1
    int wn = wid & 3;    // 0..3

    // triangular decode: k -> (ti, tj), start(ti) = 32*ti - ti*(ti-1)/2
    int k = blockIdx.x;
    int ti = (int)((65.0f - sqrtf(4225.0f - 8.0f * (float)k)) * 0.5f);
    while ((ti + 1) * 32 - ((ti + 1) * ti) / 2 <= k) ++ti;
    while (ti * 32 - (ti * (ti - 1)) / 2 > k) --ti;
    int tj = ti + (k - (ti * 32 - (ti * (ti - 1)) / 2));
    int r0 = ti * 128, c0 = tj * 128;
    bool dual = (ti != tj);
    bool postile = (tj - ti) == 16;
    const char* zb = (const char*)g_znh;   // row stride 1024B

    if (tid < 128) { rs_row[tid] = 0.0f; rs_col[tid] = 0.0f; }

    uint32_t sA0 = (uint32_t)__cvta_generic_to_shared(&sA[0][0]);
    uint32_t sB0 = (uint32_t)__cvta_generic_to_shared(&sB[0][0]);

    uint32_t aoff = (uint32_t)((64 * wm + (l & 15)) * PITCH + ((l >> 4) & 1) * 16);
    uint32_t boff = (uint32_t)((32 * wn + (l & 7) + ((l >> 4) & 1) * 8) * PITCH
                               + ((l >> 3) & 1) * 16);

    float acc[4][4][4];
#pragma unroll
    for (int a = 0; a < 4; ++a)
#pragma unroll
        for (int b = 0; b < 4; ++b)
#pragma unroll
            for (int d = 0; d < 4; ++d) acc[a][b][d] = 0.0f;

    auto load_stage = [&](int s, int buf) {
        uint32_t koff = (uint32_t)s * 64u;   // 32 bf16 per stage
#pragma unroll
        for (int m = 0; m < 4; ++m) {
            int ch = tid + m * 256;          // 0..1023 16B chunks
            int half = ch >> 9;              // 0=A, 1=B
            int e = ch & 511;
            int row = e >> 2, seg = e & 3;
            uint32_t dst = (half ? sB0 : sA0)
                         + (uint32_t)buf * (uint32_t)TILE_BYTES
                         + (uint32_t)row * PITCH + (uint32_t)seg * 16u;
            const char* src = zb + (size_t)((half ? c0 : r0) + row) * 1024u
                            + koff + (uint32_t)seg * 16u;
            asm volatile("cp.async.cg.shared.global [%0], [%1], 16;"
                         :: "r"(dst), "l"(src) : "memory");
        }
        asm volatile("cp.async.commit_group;" ::: "memory");
    };

    load_stage(0, 0);
    load_stage(1, 1);

    int buf = 0;
    for (int s = 0; s < NSTAGE; ++s) {
        asm volatile("cp.async.wait_group 1;" ::: "memory");  // stage s resident
        __syncthreads();  // all warps done with stage s-1 -> buf (s+2)%3 free

        int nbuf = buf + 2; if (nbuf >= 3) nbuf -= 3;
        if (s + 2 < NSTAGE) {
            load_stage(s + 2, nbuf);
        } else {
            asm volatile("cp.async.commit_group;" ::: "memory");
        }

        uint32_t Ab = sA0 + (uint32_t)buf * (uint32_t)TILE_BYTES;
        uint32_t Bb = sB0 + (uint32_t)buf * (uint32_t)TILE_BYTES;
#pragma unroll
        for (int ks = 0; ks < 2; ++ks) {
            uint32_t kb = (uint32_t)ks * 32u;
            uint32_t a[4][4], bb[2][4];
#pragma unroll
            for (int mt = 0; mt < 4; ++mt)
                asm volatile(
                    "ldmatrix.sync.aligned.m8n8.x4.shared.b16 {%0,%1,%2,%3}, [%4];"
                    : "=r"(a[mt][0]), "=r"(a[mt][1]), "=r"(a[mt][2]), "=r"(a[mt][3])
                    : "r"(Ab + aoff + (uint32_t)mt * (16u * PITCH) + kb));
#pragma unroll
            for (int ng = 0; ng < 2; ++ng)
                asm volatile(
                    "ldmatrix.sync.aligned.m8n8.x4.shared.b16 {%0,%1,%2,%3}, [%4];"
                    : "=r"(bb[ng][0]), "=r"(bb[ng][1]), "=r"(bb[ng][2]), "=r"(bb[ng][3])
                    : "r"(Bb + boff + (uint32_t)ng * (16u * PITCH) + kb));
#pragma unroll
            for (int mt = 0; mt < 4; ++mt)
#pragma unroll
                for (int nt = 0; nt < 4; ++nt) {
                    uint32_t b0 = bb[nt >> 1][(nt & 1) * 2];
                    uint32_t b1 = bb[nt >> 1][(nt & 1) * 2 + 1];
                    asm volatile(
                        "mma.sync.aligned.m16n8k16.row.col.f32.bf16.bf16.f32 "
                        "{%0,%1,%2,%3}, {%4,%5,%6,%7}, {%8,%9}, {%0,%1,%2,%3};"
                        : "+f"(acc[mt][nt][0]), "+f"(acc[mt][nt][1]),
                          "+f"(acc[mt][nt][2]), "+f"(acc[mt][nt][3])
                        : "r"(a[mt][0]), "r"(a[mt][1]), "r"(a[mt][2]), "r"(a[mt][3]),
                          "r"(b0), "r"(b1));
                }
        }
        ++buf; if (buf >= 3) buf = 0;
    }

    // Epilogue. D row = 64wm + 16mt + (l>>2) + 8*half ; col = 32wn + 8nt + (l&3)*2.
    float vcol[4][2];
#pragma unroll
    for (int nt = 0; nt < 4; ++nt) { vcol[nt][0] = 0.0f; vcol[nt][1] = 0.0f; }

#pragma unroll
    for (int mt = 0; mt < 4; ++mt) {
#pragma unroll
        for (int half = 0; half < 2; ++half) {
            int rl = 64 * wm + 16 * mt + (l >> 2) + 8 * half;
            int gr = r0 + rl;
            float v = 0.0f;
#pragma unroll
            for (int nt = 0; nt < 4; ++nt) {
                int gc = c0 + 32 * wn + 8 * nt + (l & 3) * 2;
                float d0 = acc[mt][nt][half * 2 + 0];
                float d1 = acc[mt][nt][half * 2 + 1];
                float e0 = exp_sim(d0);
                float e1 = exp_sim(d1);
                if (postile) {   // positive-pair diagonal lives in these tiles
                    if (gc == gr + Bz)     { g_pos[gr] = d0; g_pos[gc] = d0; }
                    if (gc + 1 == gr + Bz) { g_pos[gr] = d1; g_pos[gc + 1] = d1; }
                }
                v += (gr == gc) ? 0.0f : e0;
                v += (gr == gc + 1) ? 0.0f : e1;
                vcol[nt][0] += e0;
                vcol[nt][1] += e1;
            }
            v += __shfl_xor_sync(0xffffffffu, v, 1);
            v += __shfl_xor_sync(0xffffffffu, v, 2);
            if ((l & 3) == 0) atomicAdd(&rs_row[rl], v);
        }
    }
    if (dual) {
#pragma unroll
        for (int nt = 0; nt < 4; ++nt) {
            float cv0 = vcol[nt][0], cv1 = vcol[nt][1];
#pragma unroll
            for (int o = 4; o <= 16; o <<= 1) {
                cv0 += __shfl_xor_sync(0xffffffffu, cv0, o);
                cv1 += __shfl_xor_sync(0xffffffffu, cv1, o);
            }
            if ((l >> 2) == 0) {
                int cl = 32 * wn + 8 * nt + (l & 3) * 2;
                atomicAdd(&rs_col[cl], cv0);
                atomicAdd(&rs_col[cl + 1], cv1);
            }
        }
    }
    __syncthreads();
    if (tid < 128) {
        atomicAdd(&g_rowsum[r0 + tid], rs_row[tid]);
        if (dual) atomicAdd(&g_rowsum[c0 + tid], rs_col[tid]);
    }
}

// ---------------------------------------------------------------------------
// Kernel 3: finalize. loss_i = 2 + log(rowsum_i) - 2*pos_i ; mean into out.
// ---------------------------------------------------------------------------
__global__ void k_finalize(float* __restrict__ out) {
    int i = blockIdx.x * 256 + threadIdx.x;
    float term = 2.0f + logf(g_rowsum[i]) - 2.0f * g_pos[i];
    int l = threadIdx.x & 31;
#pragma unroll
    for (int o = 16; o > 0; o >>= 1) term += __shfl_xor_sync(0xffffffffu, term, o);
    __shared__ float red[8];
    if (l == 0) red[threadIdx.x >> 5] = term;
    __syncthreads();
    if (threadIdx.x == 0) {
        float s = 0.0f;
#pragma unroll
        for (int w = 0; w < 8; ++w) s += red[w];
        atomicAdd(out, s * (1.0f / (float)Nn));
    }
}

extern "C" void kernel_launch(void* const* d_in, const int* in_sizes, int n_in,
                              void* d_out, int out_size) {
    const float* zi = (const float*)d_in[0];
    const float* zj = (const float*)d_in[1];
    float* out = (float*)d_out;

    k_normalize<<<512, 256>>>(zi, zj, out);
    k_simexp<<<528, 256>>>();
    k_finalize<<<Nn / 256, 256>>>(out);
}

// round 8
// speedup vs baseline: 1.0809x; 1.0421x over previous
#include <cuda_runtime.h>
#include <cuda_bf16.h>
#include <cstdint>
#include <math.h>

// NT-Xent loss, B=2048, D=512, N=4096, T=0.5.
// loss = (1/N) * sum_i [ 2 + log( sum_{j != i} exp(sim_ij - 2) ) - sim_{i,partner(i)} ]
// sim = (zn zn^T)/T in [-2,2] => fixed shift 2, single pass, no row max.
// bf16 mma.sync GEMM over UPPER-TRIANGULAR tiles (sim symmetric); each
// off-diagonal tile feeds rowsum[rows] AND rowsum[cols].
// Round-5 double-buffered pipeline + __launch_bounds__(256,2) => 2 CTA/SM.

#define Bz 2048
#define Nn 4096
#define Dd 512

__device__ __nv_bfloat16 g_znh[Nn * Dd];   // bf16 normalized (4 MB, L2-resident)
__device__ float g_rowsum[Nn];             // sum_{j!=i} exp(sim_ij - 2)
__device__ float g_pos[Nn];                // dot(zn_i, zn_partner)

// ---------------------------------------------------------------------------
// exp(2a-2) on the FMA pipe (no MUFU). 2^y, y=(a-1)*2log2e in [-5.9, 0.1];
// magic-add range reduction + deg-5 poly (rel err ~3e-6).
// ---------------------------------------------------------------------------
__device__ __forceinline__ float exp_sim(float a) {
    float y = fmaf(a, 2.8853900817779268f, -2.8853900817779268f);
    float z = y + 12582912.0f;
    float f = y - (z - 12582912.0f);
    int ei = (__float_as_int(z) + (127 - 0x400000)) << 23;
    float p = fmaf(f, 1.3333558146428443e-3f, 9.6181291076284771e-3f);
    p = fmaf(f, p, 5.5504108664821580e-2f);
    p = fmaf(f, p, 2.4022650695910071e-1f);
    p = fmaf(f, p, 6.9314718055994531e-1f);
    p = fmaf(f, p, 1.0f);
    return p * __int_as_float(ei);
}

// ---------------------------------------------------------------------------
// Kernel 1: row-normalize -> bf16. One warp per row, no block sync.
// ---------------------------------------------------------------------------
__global__ __launch_bounds__(256) void k_normalize(const float* __restrict__ zi,
                                                   const float* __restrict__ zj,
                                                   float* __restrict__ out) {
    int row = (blockIdx.x * 256 + threadIdx.x) >> 5;
    int l = threadIdx.x & 31;
    const float4* src = (row < Bz)
        ? reinterpret_cast<const float4*>(zi + (size_t)row * Dd)
        : reinterpret_cast<const float4*>(zj + (size_t)(row - Bz) * Dd);
    float4 v0 = src[l];
    float4 v1 = src[l + 32];
    float4 v2 = src[l + 64];
    float4 v3 = src[l + 96];
    float ss = v0.x * v0.x + v0.y * v0.y + v0.z * v0.z + v0.w * v0.w;
    ss += v1.x * v1.x + v1.y * v1.y + v1.z * v1.z + v1.w * v1.w;
    ss += v2.x * v2.x + v2.y * v2.y + v2.z * v2.z + v2.w * v2.w;
    ss += v3.x * v3.x + v3.y * v3.y + v3.z * v3.z + v3.w * v3.w;
#pragma unroll
    for (int o = 16; o > 0; o >>= 1) ss += __shfl_xor_sync(0xffffffffu, ss, o);
    float inv = 1.0f / fmaxf(sqrtf(ss), 1e-8f);
    uint2* dst = reinterpret_cast<uint2*>(g_znh + (size_t)row * Dd);
    __nv_bfloat162 h0, h1;
    uint2 u;
    h0 = __floats2bfloat162_rn(v0.x * inv, v0.y * inv);
    h1 = __floats2bfloat162_rn(v0.z * inv, v0.w * inv);
    u.x = *reinterpret_cast<uint32_t*>(&h0); u.y = *reinterpret_cast<uint32_t*>(&h1);
    dst[l] = u;
    h0 = __floats2bfloat162_rn(v1.x * inv, v1.y * inv);
    h1 = __floats2bfloat162_rn(v1.z * inv, v1.w * inv);
    u.x = *reinterpret_cast<uint32_t*>(&h0); u.y = *reinterpret_cast<uint32_t*>(&h1);
    dst[l + 32] = u;
    h0 = __floats2bfloat162_rn(v2.x * inv, v2.y * inv);
    h1 = __floats2bfloat162_rn(v2.z * inv, v2.w * inv);
    u.x = *reinterpret_cast<uint32_t*>(&h0); u.y = *reinterpret_cast<uint32_t*>(&h1);
    dst[l + 64] = u;
    h0 = __floats2bfloat162_rn(v3.x * inv, v3.y * inv);
    h1 = __floats2bfloat162_rn(v3.z * inv, v3.w * inv);
    u.x = *reinterpret_cast<uint32_t*>(&h0); u.y = *reinterpret_cast<uint32_t*>(&h1);
    dst[l + 96] = u;
    if (l == 0) g_rowsum[row] = 0.0f;
    if (l == 0 && row == 0) out[0] = 0.0f;
}

// ---------------------------------------------------------------------------
// Kernel 2: upper-triangular fused sim-exp-rowsum (bf16).
// 528 CTAs; CTA k -> tile (ti, tj), tj >= ti, 128x128 per tile.
// 8 warps (2x4), warp tile 64x32, 16-stage K pipeline, cp.async double
// buffer. 2 CTAs/SM via launch bounds (regs capped at 128).
// ---------------------------------------------------------------------------
#define PITCH 80
#define TILE_BYTES (128 * PITCH)

__global__ __launch_bounds__(256, 2) void k_simexp() {
    __shared__ __align__(128) char sA[2][TILE_BYTES];
    __shared__ __align__(128) char sB[2][TILE_BYTES];
    __shared__ float rs_row[128];
    __shared__ float rs_col[128];

    int tid = threadIdx.x;
    int l = tid & 31;
    int wid = tid >> 5;
    int wm = wid >> 2;   // 0..1
    int wn = wid & 3;    // 0..3

    // triangular decode: k -> (ti, tj), start(ti) = 32*ti - ti*(ti-1)/2
    int k = blockIdx.x;
    int ti = (int)((65.0f - sqrtf(4225.0f - 8.0f * (float)k)) * 0.5f);
    while ((ti + 1) * 32 - ((ti + 1) * ti) / 2 <= k) ++ti;
    while (ti * 32 - (ti * (ti - 1)) / 2 > k) --ti;
    int tj = ti + (k - (ti * 32 - (ti * (ti - 1)) / 2));
    int r0 = ti * 128, c0 = tj * 128;
    bool dual = (ti != tj);
    bool postile = (tj - ti) == 16;
    const char* zb = (const char*)g_znh;   // row stride 1024B

    if (tid < 128) { rs_row[tid] = 0.0f; rs_col[tid] = 0.0f; }

    uint32_t sA0 = (uint32_t)__cvta_generic_to_shared(&sA[0][0]);
    uint32_t sB0 = (uint32_t)__cvta_generic_to_shared(&sB[0][0]);

    uint32_t aoff = (uint32_t)((64 * wm + (l & 15)) * PITCH + ((l >> 4) & 1) * 16);
    uint32_t boff = (uint32_t)((32 * wn + (l & 7) + ((l >> 4) & 1) * 8) * PITCH
                               + ((l >> 3) & 1) * 16);

    float acc[4][4][4];
#pragma unroll
    for (int a = 0; a < 4; ++a)
#pragma unroll
        for (int b = 0; b < 4; ++b)
#pragma unroll
            for (int d = 0; d < 4; ++d) acc[a][b][d] = 0.0f;

    auto load_stage = [&](int s) {
        uint32_t koff = (uint32_t)s * 64u;   // 32 bf16 per stage
#pragma unroll
        for (int m = 0; m < 4; ++m) {
            int ch = tid + m * 256;          // 0..1023 16B chunks
            int half = ch >> 9;              // 0=A, 1=B
            int e = ch & 511;
            int row = e >> 2, seg = e & 3;
            uint32_t dst = (half ? sB0 : sA0)
                         + (uint32_t)(s & 1) * (uint32_t)TILE_BYTES
                         + (uint32_t)row * PITCH + (uint32_t)seg * 16u;
            const char* src = zb + (size_t)((half ? c0 : r0) + row) * 1024u
                            + koff + (uint32_t)seg * 16u;
            asm volatile("cp.async.cg.shared.global [%0], [%1], 16;"
                         :: "r"(dst), "l"(src) : "memory");
        }
        asm volatile("cp.async.commit_group;" ::: "memory");
    };

    load_stage(0);
    for (int s = 0; s < 16; ++s) {
        if (s + 1 < 16) {
            load_stage(s + 1);
            asm volatile("cp.async.wait_group 1;" ::: "memory");
        } else {
            asm volatile("cp.async.wait_group 0;" ::: "memory");
        }
        __syncthreads();

        uint32_t Ab = sA0 + (uint32_t)(s & 1) * (uint32_t)TILE_BYTES;
        uint32_t Bb = sB0 + (uint32_t)(s & 1) * (uint32_t)TILE_BYTES;
#pragma unroll
        for (int ks = 0; ks < 2; ++ks) {
            uint32_t kb = (uint32_t)ks * 32u;
            uint32_t a[4][4], bb[2][4];
#pragma unroll
            for (int mt = 0; mt < 4; ++mt)
                asm volatile(
                    "ldmatrix.sync.aligned.m8n8.x4.shared.b16 {%0,%1,%2,%3}, [%4];"
                    : "=r"(a[mt][0]), "=r"(a[mt][1]), "=r"(a[mt][2]), "=r"(a[mt][3])
                    : "r"(Ab + aoff + (uint32_t)mt * (16u * PITCH) + kb));
#pragma unroll
            for (int ng = 0; ng < 2; ++ng)
                asm volatile(
                    "ldmatrix.sync.aligned.m8n8.x4.shared.b16 {%0,%1,%2,%3}, [%4];"
                    : "=r"(bb[ng][0]), "=r"(bb[ng][1]), "=r"(bb[ng][2]), "=r"(bb[ng][3])
                    : "r"(Bb + boff + (uint32_t)ng * (16u * PITCH) + kb));
#pragma unroll
            for (int mt = 0; mt < 4; ++mt)
#pragma unroll
                for (int nt = 0; nt < 4; ++nt) {
                    uint32_t b0 = bb[nt >> 1][(nt & 1) * 2];
                    uint32_t b1 = bb[nt >> 1][(nt & 1) * 2 + 1];
                    asm volatile(
                        "mma.sync.aligned.m16n8k16.row.col.f32.bf16.bf16.f32 "
                        "{%0,%1,%2,%3}, {%4,%5,%6,%7}, {%8,%9}, {%0,%1,%2,%3};"
                        : "+f"(acc[mt][nt][0]), "+f"(acc[mt][nt][1]),
                          "+f"(acc[mt][nt][2]), "+f"(acc[mt][nt][3])
                        : "r"(a[mt][0]), "r"(a[mt][1]), "r"(a[mt][2]), "r"(a[mt][3]),
                          "r"(b0), "r"(b1));
                }
        }
        __syncthreads();
    }

    // Epilogue. D row = 64wm + 16mt + (l>>2) + 8*half ; col = 32wn + 8nt + (l&3)*2.
    float vcol[4][2];
#pragma unroll
    for (int nt = 0; nt < 4; ++nt) { vcol[nt][0] = 0.0f; vcol[nt][1] = 0.0f; }

#pragma unroll
    for (int mt = 0; mt < 4; ++mt) {
#pragma unroll
        for (int half = 0; half < 2; ++half) {
            int rl = 64 * wm + 16 * mt + (l >> 2) + 8 * half;
            int gr = r0 + rl;
            float v = 0.0f;
#pragma unroll
            for (int nt = 0; nt < 4; ++nt) {
                int gc = c0 + 32 * wn + 8 * nt + (l & 3) * 2;
                float d0 = acc[mt][nt][half * 2 + 0];
                float d1 = acc[mt][nt][half * 2 + 1];
                float e0 = exp_sim(d0);
                float e1 = exp_sim(d1);
                if (postile) {   // positive-pair diagonal lives in these tiles
                    if (gc == gr + Bz)     { g_pos[gr] = d0; g_pos[gc] = d0; }
                    if (gc + 1 == gr + Bz) { g_pos[gr] = d1; g_pos[gc + 1] = d1; }
                }
                v += (gr == gc) ? 0.0f : e0;
                v += (gr == gc + 1) ? 0.0f : e1;
                vcol[nt][0] += e0;
                vcol[nt][1] += e1;
            }
            v += __shfl_xor_sync(0xffffffffu, v, 1);
            v += __shfl_xor_sync(0xffffffffu, v, 2);
            if ((l & 3) == 0) atomicAdd(&rs_row[rl], v);
        }
    }
    if (dual) {
#pragma unroll
        for (int nt = 0; nt < 4; ++nt) {
            float cv0 = vcol[nt][0], cv1 = vcol[nt][1];
#pragma unroll
            for (int o = 4; o <= 16; o <<= 1) {
                cv0 += __shfl_xor_sync(0xffffffffu, cv0, o);
                cv1 += __shfl_xor_sync(0xffffffffu, cv1, o);
            }
            if ((l >> 2) == 0) {
                int cl = 32 * wn + 8 * nt + (l & 3) * 2;
                atomicAdd(&rs_col[cl], cv0);
                atomicAdd(&rs_col[cl + 1], cv1);
            }
        }
    }
    __syncthreads();
    if (tid < 128) {
        atomicAdd(&g_rowsum[r0 + tid], rs_row[tid]);
        if (dual) atomicAdd(&g_rowsum[c0 + tid], rs_col[tid]);
    }
}

// ---------------------------------------------------------------------------
// Kernel 3: finalize. loss_i = 2 + log(rowsum_i) - 2*pos_i ; mean into out.
// ---------------------------------------------------------------------------
__global__ void k_finalize(float* __restrict__ out) {
    int i = blockIdx.x * 256 + threadIdx.x;
    float term = 2.0f + logf(g_rowsum[i]) - 2.0f * g_pos[i];
    int l = threadIdx.x & 31;
#pragma unroll
    for (int o = 16; o > 0; o >>= 1) term += __shfl_xor_sync(0xffffffffu, term, o);
    __shared__ float red[8];
    if (l == 0) red[threadIdx.x >> 5] = term;
    __syncthreads();
    if (threadIdx.x == 0) {
        float s = 0.0f;
#pragma unroll
        for (int w = 0; w < 8; ++w) s += red[w];
        atomicAdd(out, s * (1.0f / (float)Nn));
    }
}

extern "C" void kernel_launch(void* const* d_in, const int* in_sizes, int n_in,
                              void* d_out, int out_size) {
    const float* zi = (const float*)d_in[0];
    const float* zj = (const float*)d_in[1];
    float* out = (float*)d_out;

    k_normalize<<<512, 256>>>(zi, zj, out);
    k_simexp<<<528, 256>>>();
    k_finalize<<<Nn / 256, 256>>>(out);
}

// round 9
// speedup vs baseline: 1.1891x; 1.1001x over previous
#include <cuda_runtime.h>
#include <cuda_bf16.h>
#include <cstdint>
#include <math.h>

// NT-Xent loss, B=2048, D=512, N=4096, T=0.5.
// loss = (1/N) * sum_i [ 2 + log( sum_{j != i} exp(sim_ij - 2) ) - sim_{i,partner(i)} ]
// sim = (zn zn^T)/T in [-2,2] => fixed shift 2, single pass, no row max.
// bf16 mma.sync GEMM over UPPER-TRIANGULAR tiles (sim symmetric); each
// off-diagonal tile feeds rowsum[rows] AND rowsum[cols].
// 8 wide K-stages (64 bf16 = 128B/row) double-buffered via cp.async.

#define Bz 2048
#define Nn 4096
#define Dd 512

__device__ __nv_bfloat16 g_znh[Nn * Dd];   // bf16 normalized (4 MB, L2-resident)
__device__ float g_rowsum[Nn];             // sum_{j!=i} exp(sim_ij - 2)
__device__ float g_pos[Nn];                // dot(zn_i, zn_partner)

// ---------------------------------------------------------------------------
// exp(2a-2) on the FMA pipe (no MUFU). 2^y, y=(a-1)*2log2e in [-5.9, 0.1];
// magic-add range reduction + deg-5 poly (rel err ~3e-6).
// ---------------------------------------------------------------------------
__device__ __forceinline__ float exp_sim(float a) {
    float y = fmaf(a, 2.8853900817779268f, -2.8853900817779268f);
    float z = y + 12582912.0f;
    float f = y - (z - 12582912.0f);
    int ei = (__float_as_int(z) + (127 - 0x400000)) << 23;
    float p = fmaf(f, 1.3333558146428443e-3f, 9.6181291076284771e-3f);
    p = fmaf(f, p, 5.5504108664821580e-2f);
    p = fmaf(f, p, 2.4022650695910071e-1f);
    p = fmaf(f, p, 6.9314718055994531e-1f);
    p = fmaf(f, p, 1.0f);
    return p * __int_as_float(ei);
}

// ---------------------------------------------------------------------------
// Kernel 1: row-normalize -> bf16. TWO warps per row (half-row each),
// one smem combine. 1024 blocks x 256 thr = 262k threads (~86% occ).
// ---------------------------------------------------------------------------
__global__ __launch_bounds__(256) void k_normalize(const float* __restrict__ zi,
                                                   const float* __restrict__ zj,
                                                   float* __restrict__ out) {
    int wid = threadIdx.x >> 5;
    int l = threadIdx.x & 31;
    int row = blockIdx.x * 4 + (wid >> 1);
    int half = wid & 1;
    const float4* src = ((row < Bz)
        ? reinterpret_cast<const float4*>(zi + (size_t)row * Dd)
        : reinterpret_cast<const float4*>(zj + (size_t)(row - Bz) * Dd))
        + half * 64;                       // 64 float4 per half-row
    float4 v0 = src[l];
    float4 v1 = src[l + 32];
    float ss = v0.x * v0.x + v0.y * v0.y + v0.z * v0.z + v0.w * v0.w
             + v1.x * v1.x + v1.y * v1.y + v1.z * v1.z + v1.w * v1.w;
#pragma unroll
    for (int o = 16; o > 0; o >>= 1) ss += __shfl_xor_sync(0xffffffffu, ss, o);
    __shared__ float part[8];
    if (l == 0) part[wid] = ss;
    __syncthreads();
    float tot = part[wid & ~1] + part[wid | 1];
    float inv = 1.0f / fmaxf(sqrtf(tot), 1e-8f);
    uint2* dst = reinterpret_cast<uint2*>(g_znh + (size_t)row * Dd) + half * 64;
    __nv_bfloat162 h0, h1;
    uint2 u;
    h0 = __floats2bfloat162_rn(v0.x * inv, v0.y * inv);
    h1 = __floats2bfloat162_rn(v0.z * inv, v0.w * inv);
    u.x = *reinterpret_cast<uint32_t*>(&h0); u.y = *reinterpret_cast<uint32_t*>(&h1);
    dst[l] = u;
    h0 = __floats2bfloat162_rn(v1.x * inv, v1.y * inv);
    h1 = __floats2bfloat162_rn(v1.z * inv, v1.w * inv);
    u.x = *reinterpret_cast<uint32_t*>(&h0); u.y = *reinterpret_cast<uint32_t*>(&h1);
    dst[l + 32] = u;
    if (l == 0 && half == 0) g_rowsum[row] = 0.0f;
    if (threadIdx.x == 0 && blockIdx.x == 0) out[0] = 0.0f;
}

// ---------------------------------------------------------------------------
// Kernel 2: upper-triangular fused sim-exp-rowsum (bf16).
// 528 CTAs; CTA k -> tile (ti, tj), tj >= ti, 128x128 per tile.
// 8 warps (2x4), warp tile 64x32. 8 K-stages of 64 bf16 (128B/row),
// pitch 144, double-buffered cp.async, dynamic smem 72KB.
// ---------------------------------------------------------------------------
#define PITCH 144
#define STG_BYTES (128 * PITCH)   // 18432 per operand per stage
#define SMEM_TOTAL (4 * STG_BYTES)

__global__ __launch_bounds__(256) void k_simexp() {
    extern __shared__ __align__(128) char dsm[];
    __shared__ float rs_row[128];
    __shared__ float rs_col[128];

    int tid = threadIdx.x;
    int l = tid & 31;
    int wid = tid >> 5;
    int wm = wid >> 2;   // 0..1
    int wn = wid & 3;    // 0..3

    // triangular decode: k -> (ti, tj), start(ti) = 32*ti - ti*(ti-1)/2
    int k = blockIdx.x;
    int ti = (int)((65.0f - sqrtf(4225.0f - 8.0f * (float)k)) * 0.5f);
    while ((ti + 1) * 32 - ((ti + 1) * ti) / 2 <= k) ++ti;
    while (ti * 32 - (ti * (ti - 1)) / 2 > k) --ti;
    int tj = ti + (k - (ti * 32 - (ti * (ti - 1)) / 2));
    int r0 = ti * 128, c0 = tj * 128;
    bool dual = (ti != tj);
    bool postile = (tj - ti) == 16;
    const char* zb = (const char*)g_znh;   // row stride 1024B

    if (tid < 128) { rs_row[tid] = 0.0f; rs_col[tid] = 0.0f; }

    uint32_t sA0 = (uint32_t)__cvta_generic_to_shared(dsm);
    uint32_t sB0 = sA0 + 2u * STG_BYTES;

    uint32_t aoff = (uint32_t)((64 * wm + (l & 15)) * PITCH + ((l >> 4) & 1) * 16);
    uint32_t boff = (uint32_t)((32 * wn + (l & 7) + ((l >> 4) & 1) * 8) * PITCH
                               + ((l >> 3) & 1) * 16);

    float acc[4][4][4];
#pragma unroll
    for (int a = 0; a < 4; ++a)
#pragma unroll
        for (int b = 0; b < 4; ++b)
#pragma unroll
            for (int d = 0; d < 4; ++d) acc[a][b][d] = 0.0f;

    auto load_stage = [&](int s) {
        uint32_t koff = (uint32_t)s * 128u;  // 64 bf16 per stage
#pragma unroll
        for (int m = 0; m < 8; ++m) {
            int ch = tid + m * 256;          // 0..2047 16B chunks
            int half = ch >> 10;             // 0=A, 1=B
            int e = ch & 1023;
            int row = e >> 3, seg = e & 7;
            uint32_t dst = (half ? sB0 : sA0)
                         + (uint32_t)(s & 1) * (uint32_t)STG_BYTES
                         + (uint32_t)row * PITCH + (uint32_t)seg * 16u;
            const char* src = zb + (size_t)((half ? c0 : r0) + row) * 1024u
                            + koff + (uint32_t)seg * 16u;
            asm volatile("cp.async.cg.shared.global [%0], [%1], 16;"
                         :: "r"(dst), "l"(src) : "memory");
        }
        asm volatile("cp.async.commit_group;" ::: "memory");
    };

    load_stage(0);
    for (int s = 0; s < 8; ++s) {
        if (s + 1 < 8) {
            load_stage(s + 1);
            asm volatile("cp.async.wait_group 1;" ::: "memory");
        } else {
            asm volatile("cp.async.wait_group 0;" ::: "memory");
        }
        __syncthreads();

        uint32_t Ab = sA0 + (uint32_t)(s & 1) * (uint32_t)STG_BYTES;
        uint32_t Bb = sB0 + (uint32_t)(s & 1) * (uint32_t)STG_BYTES;
#pragma unroll
        for (int ks = 0; ks < 4; ++ks) {
            uint32_t kb = (uint32_t)ks * 32u;
            uint32_t a[4][4], bb[2][4];
#pragma unroll
            for (int mt = 0; mt < 4; ++mt)
                asm volatile(
                    "ldmatrix.sync.aligned.m8n8.x4.shared.b16 {%0,%1,%2,%3}, [%4];"
                    : "=r"(a[mt][0]), "=r"(a[mt][1]), "=r"(a[mt][2]), "=r"(a[mt][3])
                    : "r"(Ab + aoff + (uint32_t)mt * (16u * PITCH) + kb));
#pragma unroll
            for (int ng = 0; ng < 2; ++ng)
                asm volatile(
                    "ldmatrix.sync.aligned.m8n8.x4.shared.b16 {%0,%1,%2,%3}, [%4];"
                    : "=r"(bb[ng][0]), "=r"(bb[ng][1]), "=r"(bb[ng][2]), "=r"(bb[ng][3])
                    : "r"(Bb + boff + (uint32_t)ng * (16u * PITCH) + kb));
#pragma unroll
            for (int mt = 0; mt < 4; ++mt)
#pragma unroll
                for (int nt = 0; nt < 4; ++nt) {
                    uint32_t b0 = bb[nt >> 1][(nt & 1) * 2];
                    uint32_t b1 = bb[nt >> 1][(nt & 1) * 2 + 1];
                    asm volatile(
                        "mma.sync.aligned.m16n8k16.row.col.f32.bf16.bf16.f32 "
                        "{%0,%1,%2,%3}, {%4,%5,%6,%7}, {%8,%9}, {%0,%1,%2,%3};"
                        : "+f"(acc[mt][nt][0]), "+f"(acc[mt][nt][1]),
                          "+f"(acc[mt][nt][2]), "+f"(acc[mt][nt][3])
                        : "r"(a[mt][0]), "r"(a[mt][1]), "r"(a[mt][2]), "r"(a[mt][3]),
                          "r"(b0), "r"(b1));
                }
        }
        __syncthreads();
    }

    // Epilogue. D row = 64wm + 16mt + (l>>2) + 8*half ; col = 32wn + 8nt + (l&3)*2.
    float vcol[4][2];
#pragma unroll
    for (int nt = 0; nt < 4; ++nt) { vcol[nt][0] = 0.0f; vcol[nt][1] = 0.0f; }

#pragma unroll
    for (int mt = 0; mt < 4; ++mt) {
#pragma unroll
        for (int half = 0; half < 2; ++half) {
            int rl = 64 * wm + 16 * mt + (l >> 2) + 8 * half;
            int gr = r0 + rl;
            float v = 0.0f;
#pragma unroll
            for (int nt = 0; nt < 4; ++nt) {
                int gc = c0 + 32 * wn + 8 * nt + (l & 3) * 2;
                float d0 = acc[mt][nt][half * 2 + 0];
                float d1 = acc[mt][nt][half * 2 + 1];
                float e0 = exp_sim(d0);
                float e1 = exp_sim(d1);
                if (postile) {   // positive-pair diagonal lives in these tiles
                    if (gc == gr + Bz)     { g_pos[gr] = d0; g_pos[gc] = d0; }
                    if (gc + 1 == gr + Bz) { g_pos[gr] = d1; g_pos[gc + 1] = d1; }
                }
                v += (gr == gc) ? 0.0f : e0;
                v += (gr == gc + 1) ? 0.0f : e1;
                vcol[nt][0] += e0;
                vcol[nt][1] += e1;
            }
            v += __shfl_xor_sync(0xffffffffu, v, 1);
            v += __shfl_xor_sync(0xffffffffu, v, 2);
            if ((l & 3) == 0) atomicAdd(&rs_row[rl], v);
        }
    }
    if (dual) {
#pragma unroll
        for (int nt = 0; nt < 4; ++nt) {
            float cv0 = vcol[nt][0], cv1 = vcol[nt][1];
#pragma unroll
            for (int o = 4; o <= 16; o <<= 1) {
                cv0 += __shfl_xor_sync(0xffffffffu, cv0, o);
                cv1 += __shfl_xor_sync(0xffffffffu, cv1, o);
            }
            if ((l >> 2) == 0) {
                int cl = 32 * wn + 8 * nt + (l & 3) * 2;
                atomicAdd(&rs_col[cl], cv0);
                atomicAdd(&rs_col[cl + 1], cv1);
            }
        }
    }
    __syncthreads();
    if (tid < 128) {
        atomicAdd(&g_rowsum[r0 + tid], rs_row[tid]);
        if (dual) atomicAdd(&g_rowsum[c0 + tid], rs_col[tid]);
    }
}

// ---------------------------------------------------------------------------
// Kernel 3: finalize. loss_i = 2 + log(rowsum_i) - 2*pos_i ; mean into out.
// ---------------------------------------------------------------------------
__global__ void k_finalize(float* __restrict__ out) {
    int i = blockIdx.x * 256 + threadIdx.x;
    float term = 2.0f + logf(g_rowsum[i]) - 2.0f * g_pos[i];
    int l = threadIdx.x & 31;
#pragma unroll
    for (int o = 16; o > 0; o >>= 1) term += __shfl_xor_sync(0xffffffffu, term, o);
    __shared__ float red[8];
    if (l == 0) red[threadIdx.x >> 5] = term;
    __syncthreads();
    if (threadIdx.x == 0) {
        float s = 0.0f;
#pragma unroll
        for (int w = 0; w < 8; ++w) s += red[w];
        atomicAdd(out, s * (1.0f / (float)Nn));
    }
}

extern "C" void kernel_launch(void* const* d_in, const int* in_sizes, int n_in,
                              void* d_out, int out_size) {
    const float* zi = (const float*)d_in[0];
    const float* zj = (const float*)d_in[1];
    float* out = (float*)d_out;

    cudaFuncSetAttribute(k_simexp, cudaFuncAttributeMaxDynamicSharedMemorySize,
                         SMEM_TOTAL);

    k_normalize<<<Nn / 4, 256>>>(zi, zj, out);
    k_simexp<<<528, 256, SMEM_TOTAL>>>();
    k_finalize<<<Nn / 256, 256>>>(out);
}